// round 14
// baseline (speedup 1.0000x reference)
#include <cuda_runtime.h>
#include <cuda_fp16.h>
#include <cuda_bf16.h>

// Problem constants
#define B_  8
#define C_  128
#define H_  64
#define W_  64
#define HW_ (H_ * W_)
#define KS  7
#define PAD 3
#define NP  (KS * KS)   // 49 neighborhood offsets

// Padded spatial dims for k/v (3-px zero border on each side)
#define PW_  70
#define PHW_ (PW_ * PW_)   // 4900
#define NBORDER 804        // 70*70 - 64*64 border pixels per image

// Scratch: q plain (B, HW, C); k/v padded (B, PHW, C) channel-contiguous
__device__ float g_q[B_ * HW_  * C_];
__device__ float g_k[B_ * PHW_ * C_];
__device__ float g_v[B_ * PHW_ * C_];

// ---- packed f32x2 helpers (Blackwell sm_100+; PTX-only, ptxas won't emit) ----
__device__ __forceinline__ void fma2(unsigned long long& d,
                                     unsigned long long a,
                                     unsigned long long b) {
    asm("fma.rn.f32x2 %0, %1, %2, %0;" : "+l"(d) : "l"(a), "l"(b));
}
__device__ __forceinline__ unsigned long long splat2(float x) {
    unsigned long long r;
    asm("mov.b64 %0, {%1, %1};" : "=l"(r) : "f"(x));
    return r;
}
__device__ __forceinline__ float2 unpack2(unsigned long long v) {
    float2 r;
    asm("mov.b64 {%0, %1}, %2;" : "=f"(r.x), "=f"(r.y) : "l"(v));
    return r;
}
__device__ __forceinline__ unsigned long long pack2(float lo, float hi) {
    unsigned long long r;
    asm("mov.b64 %0, {%1, %2};" : "=l"(r) : "f"(lo), "f"(hi));
    return r;
}

// map i in [0, NBORDER) to border (row, col) of a 70x70 image with 64x64 interior
__device__ __forceinline__ void border_rc(int i, int& r, int& c) {
    if (i < 210)      { r = i / 70;            c = i % 70; }          // top 3 rows
    else if (i < 420) { r = 67 + (i - 210)/70; c = (i - 210) % 70; }  // bottom 3
    else {
        int j = i - 420;                       // 64 middle rows x 6 border cols
        r = 3 + j / 6;
        int cc = j % 6;
        c = (cc < 3) ? cc : (64 + cc - 3 + 3); // 0,1,2 or 67,68,69
    }
}

// ---------------------------------------------------------------------------
// Kernel 1: q/k/v = W @ x + b  (per-batch GEMM: M=128 oc, N=64-px tile, K=128)
// grid = (512 + 32, 3), block = 256, launch_bounds(256,3): <=85 regs,
// 3 blocks/SM (middle ground: R11 natural regs -> 2 blocks; R13's 64-reg
// clamp spilled into the fma chain and regressed).
// Blocks [0,512): GEMM, 4 oc x 8 px thread tile via fma.rn.f32x2, with
// register-prefetch pipelining (round-11 structure: single smem buffer).
// Blocks [512,544) with blockIdx.y==1/2: zero k/v borders (overlapped, free).
// ---------------------------------------------------------------------------
#define GEMM_BLOCKS 512
#define ZERO_BLOCKS 32
#define NCHUNK 8            // 128 / 16

__global__ __launch_bounds__(256, 3) void qkv_gemm(
    const float* __restrict__ x,
    const float* __restrict__ Wq, const float* __restrict__ bq,
    const float* __restrict__ Wk, const float* __restrict__ bk,
    const float* __restrict__ Wv, const float* __restrict__ bv)
{
    __shared__ __align__(16) float Wt[16][132];   // W^T chunk: [k][o], padded
    __shared__ __align__(16) float Xs[16][64];    // x chunk:   [k][p]

    // ---- border-zeroing blocks ----
    if (blockIdx.x >= GEMM_BLOCKS) {
        if (blockIdx.y == 0) return;
        float* dst = (blockIdx.y == 1) ? g_k : g_v;
        const int gid = (blockIdx.x - GEMM_BLOCKS) * 256 + threadIdx.x;
        const int total = B_ * NBORDER * (C_ / 4);   // float4 slots
        float4 z = make_float4(0.f, 0.f, 0.f, 0.f);
        for (int s = gid; s < total; s += ZERO_BLOCKS * 256) {
            int f4  = s & 31;            // C_/4 = 32
            int pxi = s >> 5;
            int b   = pxi / NBORDER;
            int i   = pxi - b * NBORDER;
            int r, c;
            border_rc(i, r, c);
            ((float4*)&dst[((size_t)b * PHW_ + r * PW_ + c) * C_])[f4] = z;
        }
        return;
    }

    const float* Wm;
    const float* bias;
    float* out;
    if (blockIdx.y == 0)      { Wm = Wq; bias = bq; out = g_q; }
    else if (blockIdx.y == 1) { Wm = Wk; bias = bk; out = g_k; }
    else                      { Wm = Wv; bias = bv; out = g_v; }
    const bool padded = (blockIdx.y != 0);

    const int t   = blockIdx.x;
    const int b   = t >> 6;           // 64 pixel-tiles per batch image
    const int hw0 = (t & 63) << 6;    // 64 pixels per tile
    const float* xb = x + (size_t)b * C_ * HW_;

    const int og = threadIdx.x & 31;   // out-channel group (fastest)
    const int pg = threadIdx.x >> 5;   // pixel group (one per warp)
    const int o0 = og * 4;
    const int p0 = pg * 8;

    // per-thread staging indices (fixed across chunks)
    const int w_cl = threadIdx.x & 15;        // W: k within chunk
    const int w_o  = threadIdx.x >> 4;        // W: out-channel base (o, o+16, ...)
    const int x_pp = threadIdx.x & 63;        // X: pixel
    const int x_kl = threadIdx.x >> 6;        // X: k base (kl, kl+4, ...)

    unsigned long long acc2[4][4];
#pragma unroll
    for (int i = 0; i < 4; ++i)
#pragma unroll
        for (int j = 0; j < 4; ++j) acc2[i][j] = 0ull;

    float wreg[8];
    float xreg[4];

    // prologue: fetch chunk 0
#pragma unroll
    for (int r = 0; r < 8; ++r)
        wreg[r] = Wm[(w_o + 16 * r) * C_ + w_cl];
#pragma unroll
    for (int r = 0; r < 4; ++r)
        xreg[r] = xb[(size_t)(x_kl + 4 * r) * HW_ + hw0 + x_pp];
#pragma unroll
    for (int r = 0; r < 8; ++r) Wt[w_cl][w_o + 16 * r] = wreg[r];
#pragma unroll
    for (int r = 0; r < 4; ++r) Xs[x_kl + 4 * r][x_pp] = xreg[r];
    __syncthreads();

    for (int c = 0; c < NCHUNK; ++c) {
        // prefetch next chunk into registers (LDGs overlap the fma2 loop)
        if (c < NCHUNK - 1) {
            const int kk = (c + 1) * 16;
#pragma unroll
            for (int r = 0; r < 8; ++r)
                wreg[r] = Wm[(w_o + 16 * r) * C_ + kk + w_cl];
#pragma unroll
            for (int r = 0; r < 4; ++r)
                xreg[r] = xb[(size_t)(kk + x_kl + 4 * r) * HW_ + hw0 + x_pp];
        }

#pragma unroll
        for (int k = 0; k < 16; ++k) {
            float4 w4 = *(const float4*)&Wt[k][o0];
            ulonglong2 xp0 = *(const ulonglong2*)&Xs[k][p0];
            ulonglong2 xp1 = *(const ulonglong2*)&Xs[k][p0 + 4];
            unsigned long long w2[4] = {splat2(w4.x), splat2(w4.y),
                                        splat2(w4.z), splat2(w4.w)};
            unsigned long long x2[4] = {xp0.x, xp0.y, xp1.x, xp1.y};
#pragma unroll
            for (int i = 0; i < 4; ++i)
#pragma unroll
                for (int j = 0; j < 4; ++j)
                    fma2(acc2[i][j], w2[i], x2[j]);
        }
        __syncthreads();   // all reads of current chunk done

        if (c < NCHUNK - 1) {
#pragma unroll
            for (int r = 0; r < 8; ++r) Wt[w_cl][w_o + 16 * r] = wreg[r];
#pragma unroll
            for (int r = 0; r < 4; ++r) Xs[x_kl + 4 * r][x_pp] = xreg[r];
            __syncthreads();
        }
    }

    // epilogue: add bias, write channel-contiguous (coalesced across og lanes)
    float4 bb = *(const float4*)&bias[o0];
#pragma unroll
    for (int j = 0; j < 4; ++j) {
        float2 a0 = unpack2(acc2[0][j]);
        float2 a1 = unpack2(acc2[1][j]);
        float2 a2 = unpack2(acc2[2][j]);
        float2 a3 = unpack2(acc2[3][j]);
        float4 rlo = make_float4(a0.x + bb.x, a1.x + bb.y, a2.x + bb.z, a3.x + bb.w);
        float4 rhi = make_float4(a0.y + bb.x, a1.y + bb.y, a2.y + bb.z, a3.y + bb.w);
        int px0 = hw0 + p0 + 2 * j;
#pragma unroll
        for (int e = 0; e < 2; ++e) {
            int px = px0 + e;
            size_t off;
            if (padded) {
                int row = px >> 6;
                int col = px & 63;
                off = (size_t)b * PHW_ + (size_t)(row + PAD) * PW_ + (col + PAD);
            } else {
                off = (size_t)b * HW_ + px;
            }
            *(float4*)&out[off * C_ + o0] = (e == 0) ? rlo : rhi;
        }
    }
}

// ---------------------------------------------------------------------------
// Kernel 2: local attention (best: 74.9us). 4 blocks/SM, shuffle softmax,
// predicate-free staging, fma2 pass 2. UNCHANGED (frozen).
// ---------------------------------------------------------------------------
#define TW 8
#define TH 8
#define HXW (TW + 6)        // 14
#define HXH (TH + 6)        // 14
#define HPITCH 15           // padded pitch (16B units)

__global__ __launch_bounds__(256, 4) void local_attn(float* __restrict__ out)
{
    __shared__ __align__(16) char s_raw[HXH * 8 * HPITCH * 16];  // 26.25 KB
    float4* hal4 = (float4*)s_raw;   // [hy][j(0..7)][hx] fp32, 4 ch per float4
    uint4*  hal2 = (uint4*)s_raw;    // [hy][j(0..3)][hx] half2, 8 ch per uint4

    const int tid  = threadIdx.x;
    const int ty   = tid >> 5;            // warp = pixel row
    const int lane = tid & 31;
    const int tg   = lane >> 3;           // channel quarter 0..3
    const int tx   = lane & 7;            // pixel column
    const int x0 = blockIdx.x * TW;
    const int y0 = blockIdx.y * TH;
    const int b  = blockIdx.z;
    const int gx = x0 + tx;
    const int gy = y0 + ty;

    const float* qb = g_q + (size_t)b * HW_  * C_;
    const float* kb = g_k + (size_t)b * PHW_ * C_;
    const float* vb = g_v + (size_t)b * PHW_ * C_;

    float logits[NP];
#pragma unroll
    for (int p = 0; p < NP; ++p) logits[p] = 0.f;

    // ---- Pass 1: partial logits over this thread's 32 channels (fp32 halo) ----
    for (int c0 = 0; c0 < C_; c0 += 32) {
        __syncthreads();
        for (int i = tid; i < HXH * HXW * 8; i += 256) {
            int j   = i & 7;
            int pos = i >> 3;
            int hy  = pos / HXW;
            int hx  = pos - hy * HXW;
            float4 val = *(const float4*)
                &kb[((size_t)(y0 + hy) * PW_ + (x0 + hx)) * C_ + c0 + 4 * j];
            hal4[((size_t)hy * 8 + j) * HPITCH + hx] = val;
        }
        __syncthreads();

        const float* qp = &qb[((size_t)gy * W_ + gx) * C_ + c0 + 8 * tg];
        float4 qf0 = *(const float4*)qp;
        float4 qf1 = *(const float4*)(qp + 4);
#pragma unroll
        for (int p = 0; p < NP; ++p) {
            const int dy = p / KS, dx = p - dy * KS;
            const size_t base = ((size_t)(ty + dy) * 8 + 2 * tg) * HPITCH + (tx + dx);
            float4 k0 = hal4[base];
            float4 k1 = hal4[base + HPITCH];
            float acc = fmaf(qf0.x, k0.x, fmaf(qf0.y, k0.y,
                        fmaf(qf0.z, k0.z, fmaf(qf0.w, k0.w, logits[p]))));
            logits[p] = fmaf(qf1.x, k1.x, fmaf(qf1.y, k1.y,
                        fmaf(qf1.z, k1.z, fmaf(qf1.w, k1.w, acc))));
        }
    }

    // ---- cross-quarter reduce via warp shuffles + redundant softmax ----
#pragma unroll
    for (int p = 0; p < NP; ++p) {
        logits[p] += __shfl_xor_sync(0xffffffffu, logits[p], 8);
        logits[p] += __shfl_xor_sync(0xffffffffu, logits[p], 16);
    }
    {
        float m = logits[0];
#pragma unroll
        for (int p = 1; p < NP; ++p) m = fmaxf(m, logits[p]);
        float s = 0.f;
#pragma unroll
        for (int p = 0; p < NP; ++p) {
            logits[p] = __expf(logits[p] - m);
            s += logits[p];
        }
        const float inv = 1.f / s;
#pragma unroll
        for (int p = 0; p < NP; ++p) logits[p] *= inv;
    }

    // ---- Pass 2: y(32 ch) = sum_p attn[p] * v(neighbor); half2 halo + fma2 ----
    for (int c0 = 0; c0 < C_; c0 += 32) {
        __syncthreads();
        for (int i = tid; i < HXH * HXW * 4; i += 256) {
            int j   = i & 3;
            int pos = i >> 2;
            int hy  = pos / HXW;
            int hx  = pos - hy * HXW;
            const float* vp = &vb[((size_t)(y0 + hy) * PW_ + (x0 + hx)) * C_
                                  + c0 + 8 * j];
            float4 a = *(const float4*)vp;
            float4 c = *(const float4*)(vp + 4);
            half2 h0 = __floats2half2_rn(a.x, a.y);
            half2 h1 = __floats2half2_rn(a.z, a.w);
            half2 h2 = __floats2half2_rn(c.x, c.y);
            half2 h3 = __floats2half2_rn(c.z, c.w);
            uint4 hv;
            hv.x = *(unsigned*)&h0;
            hv.y = *(unsigned*)&h1;
            hv.z = *(unsigned*)&h2;
            hv.w = *(unsigned*)&h3;
            hal2[((size_t)hy * 4 + j) * HPITCH + hx] = hv;
        }
        __syncthreads();

        unsigned long long accp[4];   // 4 packed channel-pair accumulators
#pragma unroll
        for (int i = 0; i < 4; ++i) accp[i] = 0ull;
#pragma unroll
        for (int p = 0; p < NP; ++p) {
            const int dy = p / KS, dx = p - dy * KS;
            uint4 hv = hal2[((size_t)(ty + dy) * 4 + tg) * HPITCH + (tx + dx)];
            const unsigned long long w2 = splat2(logits[p]);
            float2 f0 = __half22float2(*(half2*)&hv.x);
            float2 f1 = __half22float2(*(half2*)&hv.y);
            float2 f2 = __half22float2(*(half2*)&hv.z);
            float2 f3 = __half22float2(*(half2*)&hv.w);
            fma2(accp[0], w2, pack2(f0.x, f0.y));
            fma2(accp[1], w2, pack2(f1.x, f1.y));
            fma2(accp[2], w2, pack2(f2.x, f2.y));
            fma2(accp[3], w2, pack2(f3.x, f3.y));
        }

        const int ch = c0 + 8 * tg;
        float* op = out + ((size_t)b * C_ + ch) * HW_ + (size_t)gy * W_ + gx;
#pragma unroll
        for (int i = 0; i < 4; ++i) {
            float2 v = unpack2(accp[i]);
            op[(size_t)(2 * i)     * HW_] = v.x;
            op[(size_t)(2 * i + 1) * HW_] = v.y;
        }
    }
}

// ---------------------------------------------------------------------------
extern "C" void kernel_launch(void* const* d_in, const int* in_sizes, int n_in,
                              void* d_out, int out_size)
{
    const float* x  = (const float*)d_in[0];
    const float* Wq = (const float*)d_in[1];
    const float* bq = (const float*)d_in[2];
    const float* Wk = (const float*)d_in[3];
    const float* bk = (const float*)d_in[4];
    const float* Wv = (const float*)d_in[5];
    const float* bv = (const float*)d_in[6];
    float* out = (float*)d_out;

    dim3 ggrid(GEMM_BLOCKS + ZERO_BLOCKS, 3, 1);
    qkv_gemm<<<ggrid, 256>>>(x, Wq, bq, Wk, bk, Wv, bv);

    dim3 agrid(W_ / TW, H_ / TH, B_);
    local_attn<<<agrid, 256>>>(out);
}

// round 15
// speedup vs baseline: 1.0714x; 1.0714x over previous
#include <cuda_runtime.h>
#include <cuda_fp16.h>
#include <cuda_bf16.h>

// Problem constants
#define B_  8
#define C_  128
#define H_  64
#define W_  64
#define HW_ (H_ * W_)
#define KS  7
#define PAD 3
#define NP  (KS * KS)   // 49 neighborhood offsets

// Padded spatial dims for k/v (3-px zero border on each side)
#define PW_  70
#define PHW_ (PW_ * PW_)   // 4900
#define NBORDER 804        // 70*70 - 64*64 border pixels per image

// Scratch: q plain (B, HW, C); k padded fp32; v padded fp16 (pre-converted)
__device__ float g_q[B_ * HW_  * C_];
__device__ float g_k[B_ * PHW_ * C_];
__device__ __half g_vh[B_ * PHW_ * C_];

// ---- packed f32x2 helpers (Blackwell sm_100+; PTX-only, ptxas won't emit) ----
__device__ __forceinline__ void fma2(unsigned long long& d,
                                     unsigned long long a,
                                     unsigned long long b) {
    asm("fma.rn.f32x2 %0, %1, %2, %0;" : "+l"(d) : "l"(a), "l"(b));
}
__device__ __forceinline__ unsigned long long splat2(float x) {
    unsigned long long r;
    asm("mov.b64 %0, {%1, %1};" : "=l"(r) : "f"(x));
    return r;
}
__device__ __forceinline__ float2 unpack2(unsigned long long v) {
    float2 r;
    asm("mov.b64 {%0, %1}, %2;" : "=f"(r.x), "=f"(r.y) : "l"(v));
    return r;
}
__device__ __forceinline__ unsigned long long pack2(float lo, float hi) {
    unsigned long long r;
    asm("mov.b64 %0, {%1, %2};" : "=l"(r) : "f"(lo), "f"(hi));
    return r;
}

// map i in [0, NBORDER) to border (row, col) of a 70x70 image with 64x64 interior
__device__ __forceinline__ void border_rc(int i, int& r, int& c) {
    if (i < 210)      { r = i / 70;            c = i % 70; }          // top 3 rows
    else if (i < 420) { r = 67 + (i - 210)/70; c = (i - 210) % 70; }  // bottom 3
    else {
        int j = i - 420;                       // 64 middle rows x 6 border cols
        r = 3 + j / 6;
        int cc = j % 6;
        c = (cc < 3) ? cc : (64 + cc - 3 + 3); // 0,1,2 or 67,68,69
    }
}

// ---------------------------------------------------------------------------
// Kernel 1: q/k/v = W @ x + b  (per-batch GEMM: M=128 oc, N=64-px tile, K=128)
// grid = (512 + 32, 3), block = 256. Round-11 config (natural regs, 2 blk/SM).
// Blocks [0,512): GEMM, 4 oc x 8 px thread tile via fma.rn.f32x2, with
// register-prefetch pipelining (single smem buffer).
// V slice additionally writes a pre-converted fp16 copy g_vh for attention.
// Blocks [512,544): y==1 zeros g_k borders; y==2 unused-for-v fp32 (v fp32 no
// longer exists) -> y==0 zeros g_vh borders; y==2 idle.
// ---------------------------------------------------------------------------
#define GEMM_BLOCKS 512
#define ZERO_BLOCKS 32
#define NCHUNK 8            // 128 / 16

__global__ __launch_bounds__(256) void qkv_gemm(
    const float* __restrict__ x,
    const float* __restrict__ Wq, const float* __restrict__ bq,
    const float* __restrict__ Wk, const float* __restrict__ bk,
    const float* __restrict__ Wv, const float* __restrict__ bv)
{
    __shared__ __align__(16) float Wt[16][132];   // W^T chunk: [k][o], padded
    __shared__ __align__(16) float Xs[16][64];    // x chunk:   [k][p]

    // ---- border-zeroing blocks ----
    if (blockIdx.x >= GEMM_BLOCKS) {
        const int gid = (blockIdx.x - GEMM_BLOCKS) * 256 + threadIdx.x;
        if (blockIdx.y == 1) {
            // zero g_k borders (fp32, float4 slots)
            const int total = B_ * NBORDER * (C_ / 4);
            float4 z = make_float4(0.f, 0.f, 0.f, 0.f);
            for (int s = gid; s < total; s += ZERO_BLOCKS * 256) {
                int f4  = s & 31;            // C_/4 = 32
                int pxi = s >> 5;
                int b   = pxi / NBORDER;
                int i   = pxi - b * NBORDER;
                int r, c;
                border_rc(i, r, c);
                ((float4*)&g_k[((size_t)b * PHW_ + r * PW_ + c) * C_])[f4] = z;
            }
        } else if (blockIdx.y == 0) {
            // zero g_vh borders (fp16, uint4 slots = 8 halfs)
            const int total = B_ * NBORDER * (C_ / 8);
            uint4 z = make_uint4(0u, 0u, 0u, 0u);
            for (int s = gid; s < total; s += ZERO_BLOCKS * 256) {
                int f8  = s & 15;            // C_/8 = 16
                int pxi = s >> 4;
                int b   = pxi / NBORDER;
                int i   = pxi - b * NBORDER;
                int r, c;
                border_rc(i, r, c);
                ((uint4*)&g_vh[((size_t)b * PHW_ + r * PW_ + c) * C_])[f8] = z;
            }
        }
        return;
    }

    const float* Wm;
    const float* bias;
    if (blockIdx.y == 0)      { Wm = Wq; bias = bq; }
    else if (blockIdx.y == 1) { Wm = Wk; bias = bk; }
    else                      { Wm = Wv; bias = bv; }
    const int slice = blockIdx.y;      // 0=q, 1=k, 2=v

    const int t   = blockIdx.x;
    const int b   = t >> 6;           // 64 pixel-tiles per batch image
    const int hw0 = (t & 63) << 6;    // 64 pixels per tile
    const float* xb = x + (size_t)b * C_ * HW_;

    const int og = threadIdx.x & 31;   // out-channel group (fastest)
    const int pg = threadIdx.x >> 5;   // pixel group (one per warp)
    const int o0 = og * 4;
    const int p0 = pg * 8;

    // per-thread staging indices (fixed across chunks)
    const int w_cl = threadIdx.x & 15;        // W: k within chunk
    const int w_o  = threadIdx.x >> 4;        // W: out-channel base (o, o+16, ...)
    const int x_pp = threadIdx.x & 63;        // X: pixel
    const int x_kl = threadIdx.x >> 6;        // X: k base (kl, kl+4, ...)

    unsigned long long acc2[4][4];
#pragma unroll
    for (int i = 0; i < 4; ++i)
#pragma unroll
        for (int j = 0; j < 4; ++j) acc2[i][j] = 0ull;

    float wreg[8];
    float xreg[4];

    // prologue: fetch chunk 0
#pragma unroll
    for (int r = 0; r < 8; ++r)
        wreg[r] = Wm[(w_o + 16 * r) * C_ + w_cl];
#pragma unroll
    for (int r = 0; r < 4; ++r)
        xreg[r] = xb[(size_t)(x_kl + 4 * r) * HW_ + hw0 + x_pp];
#pragma unroll
    for (int r = 0; r < 8; ++r) Wt[w_cl][w_o + 16 * r] = wreg[r];
#pragma unroll
    for (int r = 0; r < 4; ++r) Xs[x_kl + 4 * r][x_pp] = xreg[r];
    __syncthreads();

    for (int c = 0; c < NCHUNK; ++c) {
        // prefetch next chunk into registers (LDGs overlap the fma2 loop)
        if (c < NCHUNK - 1) {
            const int kk = (c + 1) * 16;
#pragma unroll
            for (int r = 0; r < 8; ++r)
                wreg[r] = Wm[(w_o + 16 * r) * C_ + kk + w_cl];
#pragma unroll
            for (int r = 0; r < 4; ++r)
                xreg[r] = xb[(size_t)(kk + x_kl + 4 * r) * HW_ + hw0 + x_pp];
        }

#pragma unroll
        for (int k = 0; k < 16; ++k) {
            float4 w4 = *(const float4*)&Wt[k][o0];
            ulonglong2 xp0 = *(const ulonglong2*)&Xs[k][p0];
            ulonglong2 xp1 = *(const ulonglong2*)&Xs[k][p0 + 4];
            unsigned long long w2[4] = {splat2(w4.x), splat2(w4.y),
                                        splat2(w4.z), splat2(w4.w)};
            unsigned long long x2[4] = {xp0.x, xp0.y, xp1.x, xp1.y};
#pragma unroll
            for (int i = 0; i < 4; ++i)
#pragma unroll
                for (int j = 0; j < 4; ++j)
                    fma2(acc2[i][j], w2[i], x2[j]);
        }
        __syncthreads();   // all reads of current chunk done

        if (c < NCHUNK - 1) {
#pragma unroll
            for (int r = 0; r < 8; ++r) Wt[w_cl][w_o + 16 * r] = wreg[r];
#pragma unroll
            for (int r = 0; r < 4; ++r) Xs[x_kl + 4 * r][x_pp] = xreg[r];
            __syncthreads();
        }
    }

    // epilogue: add bias, write channel-contiguous (coalesced across og lanes)
    float4 bb = *(const float4*)&bias[o0];
#pragma unroll
    for (int j = 0; j < 4; ++j) {
        float2 a0 = unpack2(acc2[0][j]);
        float2 a1 = unpack2(acc2[1][j]);
        float2 a2 = unpack2(acc2[2][j]);
        float2 a3 = unpack2(acc2[3][j]);
        float4 rlo = make_float4(a0.x + bb.x, a1.x + bb.y, a2.x + bb.z, a3.x + bb.w);
        float4 rhi = make_float4(a0.y + bb.x, a1.y + bb.y, a2.y + bb.z, a3.y + bb.w);
        int px0 = hw0 + p0 + 2 * j;
#pragma unroll
        for (int e = 0; e < 2; ++e) {
            int px = px0 + e;
            float4 rv = (e == 0) ? rlo : rhi;
            if (slice == 0) {
                // q: plain (B, HW, C)
                *(float4*)&g_q[((size_t)b * HW_ + px) * C_ + o0] = rv;
            } else {
                int row = px >> 6;
                int col = px & 63;
                size_t off = (size_t)b * PHW_ + (size_t)(row + PAD) * PW_
                             + (col + PAD);
                if (slice == 1) {
                    // k: padded fp32
                    *(float4*)&g_k[off * C_ + o0] = rv;
                } else {
                    // v: padded fp16 (pre-converted; rounding identical to
                    // the former in-attention conversion)
                    half2 h01 = __floats2half2_rn(rv.x, rv.y);
                    half2 h23 = __floats2half2_rn(rv.z, rv.w);
                    uint2 hv;
                    hv.x = *(unsigned*)&h01;
                    hv.y = *(unsigned*)&h23;
                    *(uint2*)&g_vh[off * C_ + o0] = hv;
                }
            }
        }
    }
}

// ---------------------------------------------------------------------------
// Kernel 2: local attention. 4 blocks/SM, shuffle softmax, predicate-free
// staging, fma2 pass 2. Pass-2 now stages PRE-CONVERTED fp16 V (pure 16B
// copies, no cvt/pack in the hot kernel, half the pass-2 gmem bytes).
// ---------------------------------------------------------------------------
#define TW 8
#define TH 8
#define HXW (TW + 6)        // 14
#define HXH (TH + 6)        // 14
#define HPITCH 15           // padded pitch (16B units)

__global__ __launch_bounds__(256, 4) void local_attn(float* __restrict__ out)
{
    __shared__ __align__(16) char s_raw[HXH * 8 * HPITCH * 16];  // 26.25 KB
    float4* hal4 = (float4*)s_raw;   // [hy][j(0..7)][hx] fp32, 4 ch per float4
    uint4*  hal2 = (uint4*)s_raw;    // [hy][j(0..3)][hx] half2, 8 ch per uint4

    const int tid  = threadIdx.x;
    const int ty   = tid >> 5;            // warp = pixel row
    const int lane = tid & 31;
    const int tg   = lane >> 3;           // channel quarter 0..3
    const int tx   = lane & 7;            // pixel column
    const int x0 = blockIdx.x * TW;
    const int y0 = blockIdx.y * TH;
    const int b  = blockIdx.z;
    const int gx = x0 + tx;
    const int gy = y0 + ty;

    const float*  qb  = g_q  + (size_t)b * HW_  * C_;
    const float*  kb  = g_k  + (size_t)b * PHW_ * C_;
    const __half* vhb = g_vh + (size_t)b * PHW_ * C_;

    float logits[NP];
#pragma unroll
    for (int p = 0; p < NP; ++p) logits[p] = 0.f;

    // ---- Pass 1: partial logits over this thread's 32 channels (fp32 halo) ----
    for (int c0 = 0; c0 < C_; c0 += 32) {
        __syncthreads();
        for (int i = tid; i < HXH * HXW * 8; i += 256) {
            int j   = i & 7;
            int pos = i >> 3;
            int hy  = pos / HXW;
            int hx  = pos - hy * HXW;
            float4 val = *(const float4*)
                &kb[((size_t)(y0 + hy) * PW_ + (x0 + hx)) * C_ + c0 + 4 * j];
            hal4[((size_t)hy * 8 + j) * HPITCH + hx] = val;
        }
        __syncthreads();

        const float* qp = &qb[((size_t)gy * W_ + gx) * C_ + c0 + 8 * tg];
        float4 qf0 = *(const float4*)qp;
        float4 qf1 = *(const float4*)(qp + 4);
#pragma unroll
        for (int p = 0; p < NP; ++p) {
            const int dy = p / KS, dx = p - dy * KS;
            const size_t base = ((size_t)(ty + dy) * 8 + 2 * tg) * HPITCH + (tx + dx);
            float4 k0 = hal4[base];
            float4 k1 = hal4[base + HPITCH];
            float acc = fmaf(qf0.x, k0.x, fmaf(qf0.y, k0.y,
                        fmaf(qf0.z, k0.z, fmaf(qf0.w, k0.w, logits[p]))));
            logits[p] = fmaf(qf1.x, k1.x, fmaf(qf1.y, k1.y,
                        fmaf(qf1.z, k1.z, fmaf(qf1.w, k1.w, acc))));
        }
    }

    // ---- cross-quarter reduce via warp shuffles + redundant softmax ----
#pragma unroll
    for (int p = 0; p < NP; ++p) {
        logits[p] += __shfl_xor_sync(0xffffffffu, logits[p], 8);
        logits[p] += __shfl_xor_sync(0xffffffffu, logits[p], 16);
    }
    {
        float m = logits[0];
#pragma unroll
        for (int p = 1; p < NP; ++p) m = fmaxf(m, logits[p]);
        float s = 0.f;
#pragma unroll
        for (int p = 0; p < NP; ++p) {
            logits[p] = __expf(logits[p] - m);
            s += logits[p];
        }
        const float inv = 1.f / s;
#pragma unroll
        for (int p = 0; p < NP; ++p) logits[p] *= inv;
    }

    // ---- Pass 2: y(32 ch) = sum_p attn[p] * v(neighbor); fp16 halo, fma2 ----
    for (int c0 = 0; c0 < C_; c0 += 32) {
        __syncthreads();
        for (int i = tid; i < HXH * HXW * 4; i += 256) {
            int j   = i & 3;            // 8-ch sub-group (16B per uint4)
            int pos = i >> 2;
            int hy  = pos / HXW;
            int hx  = pos - hy * HXW;
            // pure copy: V already fp16 in gmem
            uint4 hv = *(const uint4*)
                &vhb[((size_t)(y0 + hy) * PW_ + (x0 + hx)) * C_ + c0 + 8 * j];
            hal2[((size_t)hy * 4 + j) * HPITCH + hx] = hv;
        }
        __syncthreads();

        unsigned long long accp[4];   // 4 packed channel-pair accumulators
#pragma unroll
        for (int i = 0; i < 4; ++i) accp[i] = 0ull;
#pragma unroll
        for (int p = 0; p < NP; ++p) {
            const int dy = p / KS, dx = p - dy * KS;
            uint4 hv = hal2[((size_t)(ty + dy) * 4 + tg) * HPITCH + (tx + dx)];
            const unsigned long long w2 = splat2(logits[p]);
            float2 f0 = __half22float2(*(half2*)&hv.x);
            float2 f1 = __half22float2(*(half2*)&hv.y);
            float2 f2 = __half22float2(*(half2*)&hv.z);
            float2 f3 = __half22float2(*(half2*)&hv.w);
            fma2(accp[0], w2, pack2(f0.x, f0.y));
            fma2(accp[1], w2, pack2(f1.x, f1.y));
            fma2(accp[2], w2, pack2(f2.x, f2.y));
            fma2(accp[3], w2, pack2(f3.x, f3.y));
        }

        const int ch = c0 + 8 * tg;
        float* op = out + ((size_t)b * C_ + ch) * HW_ + (size_t)gy * W_ + gx;
#pragma unroll
        for (int i = 0; i < 4; ++i) {
            float2 v = unpack2(accp[i]);
            op[(size_t)(2 * i)     * HW_] = v.x;
            op[(size_t)(2 * i + 1) * HW_] = v.y;
        }
    }
}

// ---------------------------------------------------------------------------
extern "C" void kernel_launch(void* const* d_in, const int* in_sizes, int n_in,
                              void* d_out, int out_size)
{
    const float* x  = (const float*)d_in[0];
    const float* Wq = (const float*)d_in[1];
    const float* bq = (const float*)d_in[2];
    const float* Wk = (const float*)d_in[3];
    const float* bk = (const float*)d_in[4];
    const float* Wv = (const float*)d_in[5];
    const float* bv = (const float*)d_in[6];
    float* out = (float*)d_out;

    dim3 ggrid(GEMM_BLOCKS + ZERO_BLOCKS, 3, 1);
    qkv_gemm<<<ggrid, 256>>>(x, Wq, bq, Wk, bk, Wv, bv);

    dim3 agrid(W_ / TW, H_ / TH, B_);
    local_attn<<<agrid, 256>>>(out);
}